// round 4
// baseline (speedup 1.0000x reference)
#include <cuda_runtime.h>

#define NL 16
#define NE 10
#define NC 128
#define NB_TOT 8192
#define NBASIS 968      // 16 linear + 136 pairs + 816 triples
#define MROW 12         // 10 floats padded to 12 (48B, 16B-aligned rows)
#define TPB 256
#define ROWS 2
#define SMEM_BYTES ((NBASIS*MROW + ROWS*NL*TPB) * 4)   // 46464 + 32768 = 79232

typedef unsigned long long ull;

// Precomputed per-channel basis->element matrix: M[c][m][e], padded rows.
__device__ __align__(16) static float g_M[(size_t)NC * NBASIS * MROW];
__device__ static unsigned int g_idx[NBASIS];

// ---------------------------------------------------------------------------
// Kernel 0: enumerate the monomial basis in the exact order the main kernel
// traverses it. type 1 = linear (index in p), 2 = pair (p<=q), 3 = triple.
// ---------------------------------------------------------------------------
__global__ void build_idx_kernel() {
    if (threadIdx.x != 0 || blockIdx.x != 0) return;
    int m = 0;
    for (int i = 0; i < NL; i++)
        g_idx[m++] = (unsigned)i | (1u << 24);
    for (int p = 0; p < NL; p++)
        for (int q = p; q < NL; q++)
            g_idx[m++] = (unsigned)p | ((unsigned)q << 8) | (2u << 24);
    for (int p = 0; p < NL; p++)
        for (int q = p; q < NL; q++)
            for (int i = q; i < NL; i++)
                g_idx[m++] = (unsigned)p | ((unsigned)q << 8) | ((unsigned)i << 16) | (3u << 24);
}

__device__ __forceinline__ int id3(int a, int b, int d) { return ((a*NL + b)*NL + d) * 23; }

// ---------------------------------------------------------------------------
// Kernel 1: build M[c][m][e] = sum over k of (symmetrized U)[m,k] * W[e,k,c].
// One thread per (m, c); consecutive threads share m (broadcast U) and walk c
// (coalesced W reads).
// ---------------------------------------------------------------------------
__global__ void build_M_kernel(const float* __restrict__ U1, const float* __restrict__ U2,
                               const float* __restrict__ U3, const float* __restrict__ W1,
                               const float* __restrict__ W2, const float* __restrict__ W3) {
    int t = blockIdx.x * blockDim.x + threadIdx.x;
    if (t >= NBASIS * NC) return;
    int m = t >> 7;
    int c = t & (NC - 1);
    unsigned enc = g_idx[m];
    int p = enc & 255, q = (enc >> 8) & 255, i = (enc >> 16) & 255;
    int type = enc >> 24;

    float row[NE];
    if (type == 1) {
        float u = U1[p];                       // K1 == 1
        #pragma unroll
        for (int e = 0; e < NE; e++) row[e] = u * W1[e*NC + c];
    } else if (type == 2) {
        float s[4];
        #pragma unroll
        for (int k = 0; k < 4; k++) {
            float v = U2[(p*NL + q)*4 + k];
            if (p != q) v += U2[(q*NL + p)*4 + k];
            s[k] = v;
        }
        #pragma unroll
        for (int e = 0; e < NE; e++) {
            float a = 0.f;
            #pragma unroll
            for (int k = 0; k < 4; k++) a += s[k] * W2[(e*4 + k)*NC + c];
            row[e] = a;
        }
    } else {
        float s[23];
        for (int k = 0; k < 23; k++) {
            float v = U3[id3(p,q,i) + k];
            if (p < q && q < i) {
                v += U3[id3(p,i,q)+k] + U3[id3(q,p,i)+k] + U3[id3(q,i,p)+k]
                   + U3[id3(i,p,q)+k] + U3[id3(i,q,p)+k];
            } else if (p == q && q < i) {
                v += U3[id3(p,i,p)+k] + U3[id3(i,p,p)+k];
            } else if (p < q && q == i) {
                v += U3[id3(q,p,q)+k] + U3[id3(q,q,p)+k];
            }
            s[k] = v;
        }
        for (int e = 0; e < NE; e++) {
            float a = 0.f;
            for (int k = 0; k < 23; k++) a += s[k] * W3[(e*23 + k)*NC + c];
            row[e] = a;
        }
    }
    float* dst = g_M + ((size_t)c * NBASIS + m) * MROW;
    #pragma unroll
    for (int e = 0; e < NE; e++) dst[e] = row[e];
    dst[10] = 0.f;
    dst[11] = 0.f;
}

// ---------------------------------------------------------------------------
// Packed fp32x2 helpers (Blackwell dual-rate fp32 FMA via PTX).
// ---------------------------------------------------------------------------
__device__ __forceinline__ void ffma2(ull& d, ull a, ull b) {
    asm("fma.rn.f32x2 %0, %1, %2, %0;" : "+l"(d) : "l"(a), "l"(b));
}
__device__ __forceinline__ ull dup2(float v) {
    ull r;
    asm("mov.b64 %0, {%1, %1};" : "=l"(r) : "f"(v));
    return r;
}

__device__ __forceinline__ void epilogue_row(const ull a[5], int b, int c,
                                             const float* __restrict__ y,
                                             float* __restrict__ out) {
    const float* yb = y + (size_t)b * NE;
    float res = 0.f;
    #pragma unroll
    for (int k = 0; k < 5; k++) {
        float lo, hi;
        asm("mov.b64 {%0, %1}, %2;" : "=f"(lo), "=f"(hi) : "l"(a[k]));
        res += lo * yb[2*k];
        res += hi * yb[2*k + 1];
    }
    out[(size_t)b * NC + c] = res;
}

// ---------------------------------------------------------------------------
// Main kernel: each thread handles ROWS=2 (b) rows for one channel c.
// acc[e] (e packed pairwise into f32x2) += phi_m * M[c][m][e].
// ---------------------------------------------------------------------------
__global__ __launch_bounds__(TPB, 2)
void contract_kernel(const float* __restrict__ x, const float* __restrict__ y,
                     float* __restrict__ out) {
    extern __shared__ __align__(16) float smem[];
    float* sM = smem;                       // NBASIS*MROW floats
    float* sx = smem + NBASIS * MROW;       // [ROWS][NL][TPB]

    const int c   = blockIdx.y;
    const int b0  = blockIdx.x * (TPB * ROWS);
    const int tid = threadIdx.x;

    // Stage M[c] into shared (vectorized, broadcast-reused by all warps).
    {
        const float4* src = reinterpret_cast<const float4*>(g_M + (size_t)c * NBASIS * MROW);
        float4* dst = reinterpret_cast<float4*>(sM);
        const int n4 = NBASIS * MROW / 4;   // 2904
        for (int j = tid; j < n4; j += TPB) dst[j] = src[j];
    }
    // Stage x rows into shared, lane-strided (conflict-free dynamic indexing).
    #pragma unroll
    for (int r = 0; r < ROWS; r++) {
        int b = b0 + r * TPB + tid;
        const float4* xr = reinterpret_cast<const float4*>(x + ((size_t)b * NC + c) * NL);
        #pragma unroll
        for (int j = 0; j < 4; j++) {
            float4 v = xr[j];
            sx[r*NL*TPB + (4*j + 0)*TPB + tid] = v.x;
            sx[r*NL*TPB + (4*j + 1)*TPB + tid] = v.y;
            sx[r*NL*TPB + (4*j + 2)*TPB + tid] = v.z;
            sx[r*NL*TPB + (4*j + 3)*TPB + tid] = v.w;
        }
    }
    __syncthreads();

    ull a0[5] = {0, 0, 0, 0, 0};
    ull a1[5] = {0, 0, 0, 0, 0};
    const float* x0 = sx + tid;
    const float* x1 = sx + NL * TPB + tid;
    const float* mp = sM;

#define ACCUM(PH0, PH1) do {                                                   \
        const ulonglong2* mv = reinterpret_cast<const ulonglong2*>(mp);        \
        ulonglong2 mA = mv[0];                                                 \
        ulonglong2 mB = mv[1];                                                 \
        ull mC = reinterpret_cast<const ull*>(mp)[4];                          \
        ull d0 = dup2(PH0);                                                    \
        ull d1 = dup2(PH1);                                                    \
        ffma2(a0[0], d0, mA.x); ffma2(a1[0], d1, mA.x);                        \
        ffma2(a0[1], d0, mA.y); ffma2(a1[1], d1, mA.y);                        \
        ffma2(a0[2], d0, mB.x); ffma2(a1[2], d1, mB.x);                        \
        ffma2(a0[3], d0, mB.y); ffma2(a1[3], d1, mB.y);                        \
        ffma2(a0[4], d0, mC);   ffma2(a1[4], d1, mC);                          \
        mp += MROW;                                                            \
    } while (0)

    // --- linear basis (16) ---
    #pragma unroll
    for (int i = 0; i < NL; i++) {
        float p0 = x0[i*TPB], p1 = x1[i*TPB];
        ACCUM(p0, p1);
    }
    // --- pair basis (136), p <= q ---
    #pragma unroll 1
    for (int p = 0; p < NL; p++) {
        float xp0 = x0[p*TPB], xp1 = x1[p*TPB];
        for (int q = p; q < NL; q++) {
            float f0 = xp0 * x0[q*TPB];
            float f1 = xp1 * x1[q*TPB];
            ACCUM(f0, f1);
        }
    }
    // --- triple basis (816), p <= q <= i ---
    #pragma unroll 1
    for (int p = 0; p < NL; p++) {
        float xp0 = x0[p*TPB], xp1 = x1[p*TPB];
        #pragma unroll 1
        for (int q = p; q < NL; q++) {
            float pq0 = xp0 * x0[q*TPB];
            float pq1 = xp1 * x1[q*TPB];
            for (int i = q; i < NL; i++) {
                float f0 = pq0 * x0[i*TPB];
                float f1 = pq1 * x1[i*TPB];
                ACCUM(f0, f1);
            }
        }
    }
#undef ACCUM

    epilogue_row(a0, b0 + 0*TPB + tid, c, y, out);
    epilogue_row(a1, b0 + 1*TPB + tid, c, y, out);
}

// ---------------------------------------------------------------------------
extern "C" void kernel_launch(void* const* d_in, const int* in_sizes, int n_in,
                              void* d_out, int out_size) {
    // Identify inputs by element count (all distinct for this problem).
    const float *x = 0, *y = 0, *U1 = 0, *U2 = 0, *U3 = 0, *W1 = 0, *W2 = 0, *W3 = 0;
    for (int i = 0; i < n_in; i++) {
        const float* p = (const float*)d_in[i];
        switch (in_sizes[i]) {
            case 8192 * 128 * 16:   x  = p; break;   // (B,C,L)
            case 8192 * 10:         y  = p; break;   // (B,E)
            case 16:                U1 = p; break;   // (L,K1)
            case 16 * 16 * 4:       U2 = p; break;   // (L,L,K2)
            case 16 * 16 * 16 * 23: U3 = p; break;   // (L,L,L,K3)
            case 10 * 1 * 128:      W1 = p; break;   // (E,K1,C)
            case 10 * 4 * 128:      W2 = p; break;   // (E,K2,C)
            case 10 * 23 * 128:     W3 = p; break;   // (E,K3,C)
        }
    }

    cudaFuncSetAttribute(contract_kernel,
                         cudaFuncAttributeMaxDynamicSharedMemorySize, SMEM_BYTES);

    build_idx_kernel<<<1, 32>>>();
    const int tot = NBASIS * NC;
    build_M_kernel<<<(tot + 255) / 256, 256>>>(U1, U2, U3, W1, W2, W3);

    dim3 grid(NB_TOT / (TPB * ROWS), NC);   // (16, 128)
    contract_kernel<<<grid, TPB, SMEM_BYTES>>>(x, y, (float*)d_out);
}

// round 5
// speedup vs baseline: 1.2243x; 1.2243x over previous
#include <cuda_runtime.h>

#define NL 16
#define NE 10
#define NC 128
#define NB_TOT 8192
#define NBASIS 968      // 16 linear + 136 pairs + 816 triples (Horner order)
#define MROW 12         // 10 floats padded to 12 (48B rows, 16B aligned)
#define TPB 256
#define ROWS 2

typedef unsigned long long ull;

// Precomputed per-channel basis->element matrix in Horner traversal order.
__device__ __align__(16) static float g_M[(size_t)NC * NBASIS * MROW];

__device__ __forceinline__ int id3(int a, int b, int d) { return ((a*NL + b)*NL + d) * 23; }

// ---------------------------------------------------------------------------
// build_M: one thread per (m, c). Decodes Horner-order row index m into
// (type, p, q, i), symmetrizes U over index permutations, contracts with W.
// Horner order: for p { M1(p); for q>=p { M2(p,q); for i>=q { M3(p,q,i) } } }
// ---------------------------------------------------------------------------
__global__ void build_M_kernel(const float* __restrict__ U1, const float* __restrict__ U2,
                               const float* __restrict__ U3, const float* __restrict__ W1,
                               const float* __restrict__ W2, const float* __restrict__ W3) {
    int t = blockIdx.x * blockDim.x + threadIdx.x;
    if (t >= NBASIS * NC) return;
    int m = t >> 7;
    int c = t & (NC - 1);

    // Decode Horner position.
    int p = 0;
    for (;;) {
        int np = NL - p;                         // #q values
        int blk = 1 + np + np * (np + 1) / 2;    // M1 + per-q (M2 + triples)
        if (m < blk) break;
        m -= blk; p++;
    }
    int type, q = 0, i = 0;
    if (m == 0) {
        type = 1;
    } else {
        m -= 1;
        q = p;
        for (;;) {
            int blk = 1 + (NL - q);
            if (m < blk) break;
            m -= blk; q++;
        }
        if (m == 0) type = 2;
        else { type = 3; i = q + (m - 1); }
    }

    float row[NE];
    if (type == 1) {
        float u = U1[p];                          // K1 == 1
        #pragma unroll
        for (int e = 0; e < NE; e++) row[e] = u * W1[e*NC + c];
    } else if (type == 2) {
        float s[4];
        #pragma unroll
        for (int k = 0; k < 4; k++) {
            float v = U2[(p*NL + q)*4 + k];
            if (p != q) v += U2[(q*NL + p)*4 + k];
            s[k] = v;
        }
        #pragma unroll
        for (int e = 0; e < NE; e++) {
            float a = 0.f;
            #pragma unroll
            for (int k = 0; k < 4; k++) a += s[k] * W2[(e*4 + k)*NC + c];
            row[e] = a;
        }
    } else {
        float s[23];
        for (int k = 0; k < 23; k++) {
            float v = U3[id3(p,q,i) + k];
            if (p < q && q < i) {
                v += U3[id3(p,i,q)+k] + U3[id3(q,p,i)+k] + U3[id3(q,i,p)+k]
                   + U3[id3(i,p,q)+k] + U3[id3(i,q,p)+k];
            } else if (p == q && q < i) {
                v += U3[id3(p,i,p)+k] + U3[id3(i,p,p)+k];
            } else if (p < q && q == i) {
                v += U3[id3(q,p,q)+k] + U3[id3(q,q,p)+k];
            }
            s[k] = v;
        }
        for (int e = 0; e < NE; e++) {
            float a = 0.f;
            for (int k = 0; k < 23; k++) a += s[k] * W3[(e*23 + k)*NC + c];
            row[e] = a;
        }
    }

    // recompute the flat row index (t>>7) for the store
    int mrow = t >> 7;
    float* dst = g_M + ((size_t)c * NBASIS + mrow) * MROW;
    #pragma unroll
    for (int e = 0; e < NE; e++) dst[e] = row[e];
    dst[10] = 0.f;
    dst[11] = 0.f;
}

// ---------------------------------------------------------------------------
// Packed fp32x2 helpers.
// ---------------------------------------------------------------------------
__device__ __forceinline__ void ffma2(ull& d, ull a, ull b) {
    asm("fma.rn.f32x2 %0, %1, %2, %0;" : "+l"(d) : "l"(a), "l"(b));
}
__device__ __forceinline__ ull dup2(float v) {
    ull r;
    asm("mov.b64 %0, {%1, %1};" : "=l"(r) : "f"(v));
    return r;
}

struct Row { ull a, b, c, d, e; };

__device__ __forceinline__ Row load_row(const float* mp) {
    ulonglong2 u0 = *reinterpret_cast<const ulonglong2*>(mp);
    ulonglong2 u1 = *reinterpret_cast<const ulonglong2*>(mp + 4);
    ull u2 = *reinterpret_cast<const ull*>(mp + 8);
    Row r; r.a = u0.x; r.b = u0.y; r.c = u1.x; r.d = u1.y; r.e = u2;
    return r;
}
__device__ __forceinline__ void fma_row(Row& acc, ull d, const Row& m) {
    ffma2(acc.a, d, m.a);
    ffma2(acc.b, d, m.b);
    ffma2(acc.c, d, m.c);
    ffma2(acc.d, d, m.d);
    ffma2(acc.e, d, m.e);
}

__device__ __forceinline__ void epilogue_row(const Row& a, int b, int c,
                                             const float* __restrict__ y,
                                             float* __restrict__ out) {
    const float* yb = y + (size_t)b * NE;
    ull v[5] = {a.a, a.b, a.c, a.d, a.e};
    float res = 0.f;
    #pragma unroll
    for (int k = 0; k < 5; k++) {
        float lo, hi;
        asm("mov.b64 {%0, %1}, %2;" : "=f"(lo), "=f"(hi) : "l"(v[k]));
        res += lo * yb[2*k];
        res += hi * yb[2*k + 1];
    }
    out[(size_t)b * NC + c] = res;
}

// ---------------------------------------------------------------------------
// Main kernel: fully unrolled Horner evaluation. Each thread: 2 b-rows,
// one channel c. x lives in registers (static indices after unroll); M is
// staged in static shared and walked sequentially in Horner order.
// ---------------------------------------------------------------------------
__global__ __launch_bounds__(TPB, 2)
void contract_kernel(const float* __restrict__ x, const float* __restrict__ y,
                     float* __restrict__ out) {
    __shared__ __align__(16) float sM[NBASIS * MROW];

    const int c   = blockIdx.y;
    const int b0  = blockIdx.x * (TPB * ROWS);
    const int tid = threadIdx.x;

    // Stage M[c] into shared (float4, broadcast-reused by all warps).
    {
        const float4* src = reinterpret_cast<const float4*>(g_M + (size_t)c * NBASIS * MROW);
        float4* dst = reinterpret_cast<float4*>(sM);
        const int n4 = NBASIS * MROW / 4;   // 2904
        for (int j = tid; j < n4; j += TPB) dst[j] = src[j];
    }

    // Load the thread's two x rows straight into registers.
    float xa[NL], xb[NL];
    {
        const float4* xr0 = reinterpret_cast<const float4*>(
            x + ((size_t)(b0 + tid) * NC + c) * NL);
        const float4* xr1 = reinterpret_cast<const float4*>(
            x + ((size_t)(b0 + TPB + tid) * NC + c) * NL);
        #pragma unroll
        for (int j = 0; j < 4; j++) {
            float4 v0 = xr0[j];
            xa[4*j+0] = v0.x; xa[4*j+1] = v0.y; xa[4*j+2] = v0.z; xa[4*j+3] = v0.w;
            float4 v1 = xr1[j];
            xb[4*j+0] = v1.x; xb[4*j+1] = v1.y; xb[4*j+2] = v1.z; xb[4*j+3] = v1.w;
        }
    }
    __syncthreads();

    Row acc0; acc0.a = acc0.b = acc0.c = acc0.d = acc0.e = 0ull;
    Row acc1 = acc0;

    const float* mp = sM;
    #pragma unroll
    for (int p = 0; p < NL; p++) {
        Row ap0 = load_row(mp);          // init with M1[p]
        Row ap1 = ap0;
        mp += MROW;
        #pragma unroll
        for (int q = p; q < NL; q++) {
            Row s0 = load_row(mp);       // init with M2[p,q]
            Row s1 = s0;
            mp += MROW;
            #pragma unroll
            for (int i = q; i < NL; i++) {
                Row m3 = load_row(mp);
                mp += MROW;
                fma_row(s0, dup2(xa[i]), m3);
                fma_row(s1, dup2(xb[i]), m3);
            }
            fma_row(ap0, dup2(xa[q]), s0);
            fma_row(ap1, dup2(xb[q]), s1);
        }
        fma_row(acc0, dup2(xa[p]), ap0);
        fma_row(acc1, dup2(xb[p]), ap1);
    }

    epilogue_row(acc0, b0 + tid,       c, y, out);
    epilogue_row(acc1, b0 + TPB + tid, c, y, out);
}

// ---------------------------------------------------------------------------
extern "C" void kernel_launch(void* const* d_in, const int* in_sizes, int n_in,
                              void* d_out, int out_size) {
    const float *x = 0, *y = 0, *U1 = 0, *U2 = 0, *U3 = 0, *W1 = 0, *W2 = 0, *W3 = 0;
    for (int i = 0; i < n_in; i++) {
        const float* p = (const float*)d_in[i];
        switch (in_sizes[i]) {
            case 8192 * 128 * 16:   x  = p; break;   // (B,C,L)
            case 8192 * 10:         y  = p; break;   // (B,E)
            case 16:                U1 = p; break;   // (L,K1)
            case 16 * 16 * 4:       U2 = p; break;   // (L,L,K2)
            case 16 * 16 * 16 * 23: U3 = p; break;   // (L,L,L,K3)
            case 10 * 1 * 128:      W1 = p; break;   // (E,K1,C)
            case 10 * 4 * 128:      W2 = p; break;   // (E,K2,C)
            case 10 * 23 * 128:     W3 = p; break;   // (E,K3,C)
        }
    }

    const int tot = NBASIS * NC;
    build_M_kernel<<<(tot + 255) / 256, 256>>>(U1, U2, U3, W1, W2, W3);

    dim3 grid(NB_TOT / (TPB * ROWS), NC);   // (16, 128)
    contract_kernel<<<grid, TPB>>>(x, y, (float*)d_out);
}